// round 13
// baseline (speedup 1.0000x reference)
#include <cuda_runtime.h>
#include <cuda_bf16.h>
#include <cuda_fp16.h>
#include <cstdint>

#define NN 131072
#define EE 2097152

// ---------------- device scratch (static; no allocation allowed) ----------------
__device__ float2 g_dc[NN];            // (deg accumulator, count accumulator) — one red.v2 target
__device__ float  g_dis[NN];           // rsqrt(deg), derived in scan3
__device__ int    g_cnt[NN];           // int count, derived in scan3
__device__ int    g_rowptr[NN];        // exclusive scan of counts
__device__ int    g_cur[NN];           // scatter cursor
__device__ int    g_blksum[128];
__device__ int    g_blkoff[128];
__device__ int2   g_csr[EE];           // (src, __float_as_int(norm)), grouped by dst
__device__ __half g_xh[NN * 64];       // fp16 copy of x (one 128B line per node)
__device__ float  g_aggx[NN * 64];     // A_norm @ x  (fp32 for GEMM1)
__device__ float  g_h1[NN * 128];      // relu(agg(x) @ W1 + b1)
__device__ __half g_h2h[NN * 64];      // h1 @ W2  (fp16 for agg2 gathers)
__device__ float  g_h2[NN * 64];       // A_norm @ h2t (fp32 for FC)

// ---------------- init ----------------
__global__ void k_init() {
    int i = blockIdx.x * blockDim.x + threadIdx.x;
    if (i < NN) g_dc[i] = make_float2(1.0f, 0.0f);   // self-loop weight = 1, count 0
}

// ---------------- degree + histogram: ONE vector reduction per edge ----------------
__global__ void k_deg_hist(const int* __restrict__ ei, const float* __restrict__ ew) {
    int e = blockIdx.x * blockDim.x + threadIdx.x;
    if (e < EE) {
        int d = ei[EE + e];
        float w = ew[e];
        asm volatile("red.global.add.v2.f32 [%0], {%1,%2};"
                     :: "l"(&g_dc[d]), "f"(w), "f"(1.0f) : "memory");
    }
}

// ---------------- x -> fp16 (coalesced convert) ----------------
__global__ void k_x2h(const float* __restrict__ X) {
    int t = blockIdx.x * blockDim.x + threadIdx.x;   // NN*16 threads, float4 each
    if (t >= NN * 16) return;
    float4 v = ((const float4*)X)[t];
    __half2* O = (__half2*)g_xh;
    O[2 * t]     = __floats2half2_rn(v.x, v.y);
    O[2 * t + 1] = __floats2half2_rn(v.z, v.w);
}

// ---------------- exclusive scan of counts (128 blocks x 1024 elems) ----------------
__global__ void k_scan1() {
    __shared__ int warp_s[8];
    int b = blockIdx.x, t = threadIdx.x;
    int base = b * 1024 + t * 4;
    const float4* D4 = (const float4*)g_dc;
    float4 f0 = D4[base / 2];          // g_dc[base], g_dc[base+1]
    float4 f1 = D4[base / 2 + 1];      // g_dc[base+2], g_dc[base+3]
    int c0 = (int)f0.y, c1 = (int)f0.w, c2 = (int)f1.y, c3 = (int)f1.w;
    int s0 = c0, s1 = s0 + c1, s2 = s1 + c2, s3 = s2 + c3;
    int tsum = s3;
    int lane = t & 31, warp = t >> 5;
    int v = tsum;
    #pragma unroll
    for (int off = 1; off < 32; off <<= 1) {
        int u = __shfl_up_sync(0xffffffffu, v, off);
        if (lane >= off) v += u;
    }
    if (lane == 31) warp_s[warp] = v;
    __syncthreads();
    if (t < 8) {
        int x = warp_s[t];
        #pragma unroll
        for (int off = 1; off < 8; off <<= 1) {
            int u = __shfl_up_sync(0xffu, x, off);
            if (t >= off) x += u;
        }
        warp_s[t] = x;
    }
    __syncthreads();
    int woff = (warp > 0) ? warp_s[warp - 1] : 0;
    int texcl = woff + v - tsum;
    g_rowptr[base + 0] = texcl;
    g_rowptr[base + 1] = texcl + s0;
    g_rowptr[base + 2] = texcl + s1;
    g_rowptr[base + 3] = texcl + s2;
    if (t == 255) g_blksum[b] = woff + v;
}

__global__ void k_scan2() {
    __shared__ int sh[128];
    int t = threadIdx.x;
    int v = g_blksum[t];
    sh[t] = v;
    __syncthreads();
    for (int off = 1; off < 128; off <<= 1) {
        int u = (t >= off) ? sh[t - off] : 0;
        __syncthreads();
        sh[t] += u;
        __syncthreads();
    }
    g_blkoff[t] = sh[t] - v;   // exclusive
}

__global__ void k_scan3_dis() {
    int i = blockIdx.x * blockDim.x + threadIdx.x;
    if (i < NN) {
        int r = g_rowptr[i] + g_blkoff[i >> 10];
        g_rowptr[i] = r;
        g_cur[i] = r;
        float2 dc = g_dc[i];
        g_dis[i] = rsqrtf(dc.x);         // deg >= 1 (self-loop)
        g_cnt[i] = (int)dc.y;
    }
}

// ---------------- scatter edges into CSR, norm computed inline ----------------
__global__ void k_scatter(const int* __restrict__ ei, const float* __restrict__ ew) {
    int e = blockIdx.x * blockDim.x + threadIdx.x;
    if (e >= EE) return;
    int s = ei[e], d = ei[EE + e];
    float nrm = g_dis[s] * ew[e] * g_dis[d];
    int pos = atomicAdd(&g_cur[d], 1);
    g_csr[pos] = make_int2(s, __float_as_int(nrm));
}

// ---------------- CSR gather aggregation (fp16 in, fp32 out): one warp/node --------
// Lanes cooperatively load 32 CSR entries (coalesced), broadcast via shfl (register,
// not memory), gathers issued 2-deep before their consuming fmas -> MLP >= 4.
__global__ void k_agg_csr_h(const __half* __restrict__ Xh, float* __restrict__ Out) {
    int warp = threadIdx.x >> 5;
    int lane = threadIdx.x & 31;
    int node = blockIdx.x * 8 + warp;
    const __half2* X2 = (const __half2*)Xh;

    float sn = g_dis[node];
    sn = sn * sn;
    float2 xs = __half22float2(X2[node * 32 + lane]);
    float2 acc0 = make_float2(sn * xs.x, sn * xs.y);
    float2 acc1 = make_float2(0.f, 0.f);

    int beg = g_rowptr[node];
    int deg = g_cnt[node];

    for (int base = 0; base < deg; base += 32) {
        int n = min(32, deg - base);
        int2 entry = make_int2(0, 0);
        if (lane < n) entry = g_csr[beg + base + lane];   // coalesced 256B
        int j = 0;
        #pragma unroll 2
        for (; j + 2 <= n; j += 2) {
            int s0 = __shfl_sync(0xffffffffu, entry.x, j);
            int b0 = __shfl_sync(0xffffffffu, entry.y, j);
            int s1 = __shfl_sync(0xffffffffu, entry.x, j + 1);
            int b1 = __shfl_sync(0xffffffffu, entry.y, j + 1);
            float2 v0 = __half22float2(X2[s0 * 32 + lane]);   // both loads issue
            float2 v1 = __half22float2(X2[s1 * 32 + lane]);   // before fmas
            float n0 = __int_as_float(b0);
            float n1 = __int_as_float(b1);
            acc0.x = fmaf(n0, v0.x, acc0.x);
            acc0.y = fmaf(n0, v0.y, acc0.y);
            acc1.x = fmaf(n1, v1.x, acc1.x);
            acc1.y = fmaf(n1, v1.y, acc1.y);
        }
        if (j < n) {
            int s0 = __shfl_sync(0xffffffffu, entry.x, j);
            int b0 = __shfl_sync(0xffffffffu, entry.y, j);
            float2 v0 = __half22float2(X2[s0 * 32 + lane]);
            float n0 = __int_as_float(b0);
            acc0.x = fmaf(n0, v0.x, acc0.x);
            acc0.y = fmaf(n0, v0.y, acc0.y);
        }
    }
    acc0.x += acc1.x;
    acc0.y += acc1.y;
    ((float2*)Out)[node * 32 + lane] = acc0;
}

// ---------------- tf32 tensor-core GEMM: Y[N,NC] = X[N,K] @ W[K,NC] ----------------
__device__ __forceinline__ unsigned int cvt_tf32(float f) {
    unsigned int o;
    asm("cvt.rna.tf32.f32 %0, %1;" : "=r"(o) : "f"(f));
    return o;
}

__device__ __forceinline__ void mma_tf32(float* c, unsigned int a0, unsigned int a1,
                                         unsigned int a2, unsigned int a3,
                                         unsigned int b0, unsigned int b1) {
    asm volatile("mma.sync.aligned.m16n8k8.row.col.f32.tf32.tf32.f32 "
                 "{%0,%1,%2,%3}, {%4,%5,%6,%7}, {%8,%9}, {%0,%1,%2,%3};"
                 : "+f"(c[0]), "+f"(c[1]), "+f"(c[2]), "+f"(c[3])
                 : "r"(a0), "r"(a1), "r"(a2), "r"(a3), "r"(b0), "r"(b1));
}

template<int K, int NC, bool BIAS_RELU, bool OUT_HALF>
__global__ void gemm_tc(const float* __restrict__ X, const float* __restrict__ W,
                        const float* __restrict__ bias, void* __restrict__ Yv) {
    constexpr int SX = K + 4;
    constexpr int SW = NC + 8;
    constexpr int NT = NC / 8;
    extern __shared__ float smem[];
    float* sX = smem;               // 128 * SX
    float* sW = smem + 128 * SX;    // K * SW

    int tid = threadIdx.x, lane = tid & 31, warp = tid >> 5;
    int row0 = blockIdx.x * 128;

    #pragma unroll 4
    for (int idx = tid; idx < 128 * (K / 4); idx += 256) {
        int r = idx / (K / 4);
        int c4 = idx % (K / 4);
        float4 v = ((const float4*)(X + (size_t)(row0 + r) * K))[c4];
        *(float4*)&sX[r * SX + c4 * 4] = v;
    }
    #pragma unroll 4
    for (int idx = tid; idx < K * (NC / 4); idx += 256) {
        int r = idx / (NC / 4);
        int c4 = idx % (NC / 4);
        float4 v = ((const float4*)(W + r * NC))[c4];
        *(float4*)&sW[r * SW + c4 * 4] = v;
    }
    __syncthreads();

    float acc[NT][4];
    #pragma unroll
    for (int t = 0; t < NT; t++)
        #pragma unroll
        for (int i = 0; i < 4; i++) acc[t][i] = 0.0f;

    int ar = warp * 16 + (lane >> 2);
    int ak = lane & 3;
    int bk = lane & 3;
    int bn = lane >> 2;

    #pragma unroll
    for (int ks = 0; ks < K / 8; ks++) {
        int k0 = ks * 8;
        unsigned int a0 = cvt_tf32(sX[ar * SX + k0 + ak]);
        unsigned int a1 = cvt_tf32(sX[(ar + 8) * SX + k0 + ak]);
        unsigned int a2 = cvt_tf32(sX[ar * SX + k0 + ak + 4]);
        unsigned int a3 = cvt_tf32(sX[(ar + 8) * SX + k0 + ak + 4]);
        #pragma unroll
        for (int t = 0; t < NT; t++) {
            unsigned int b0 = cvt_tf32(sW[(k0 + bk) * SW + t * 8 + bn]);
            unsigned int b1 = cvt_tf32(sW[(k0 + bk + 4) * SW + t * 8 + bn]);
            mma_tf32(acc[t], a0, a1, a2, a3, b0, b1);
        }
    }

    int orow = row0 + ar;
    #pragma unroll
    for (int t = 0; t < NT; t++) {
        int col = t * 8 + 2 * (lane & 3);
        float b0 = 0.f, b1 = 0.f;
        if (BIAS_RELU) { b0 = bias[col]; b1 = bias[col + 1]; }
        float2 v0 = make_float2(acc[t][0] + b0, acc[t][1] + b1);
        float2 v1 = make_float2(acc[t][2] + b0, acc[t][3] + b1);
        if (BIAS_RELU) {
            v0.x = fmaxf(v0.x, 0.f); v0.y = fmaxf(v0.y, 0.f);
            v1.x = fmaxf(v1.x, 0.f); v1.y = fmaxf(v1.y, 0.f);
        }
        if (OUT_HALF) {
            __half2* Y = (__half2*)Yv;
            Y[((size_t)orow * NC + col) / 2] = __floats2half2_rn(v0.x, v0.y);
            Y[((size_t)(orow + 8) * NC + col) / 2] = __floats2half2_rn(v1.x, v1.y);
        } else {
            float* Y = (float*)Yv;
            *(float2*)&Y[(size_t)orow * NC + col] = v0;
            *(float2*)&Y[(size_t)(orow + 8) * NC + col] = v1;
        }
    }
}

// ---------------- FC + softmax (fuses layer-2 bias + relu) ----------------
__global__ void fc_softmax(const float* __restrict__ H, const float* __restrict__ Wfc,
                           const float* __restrict__ bfc, const float* __restrict__ b2,
                           float* __restrict__ out) {
    int g = blockIdx.x;
    int tid = threadIdx.x;      // 256
    const float* hrow = H + g * 8192;

    float a0 = 0.f, a1 = 0.f, a2 = 0.f, a3 = 0.f;
    for (int j = tid; j < 8192; j += 256) {
        float v = hrow[j] + b2[j & 63];
        v = fmaxf(v, 0.f);
        float4 w = __ldg((const float4*)Wfc + j);
        a0 = fmaf(v, w.x, a0);
        a1 = fmaf(v, w.y, a1);
        a2 = fmaf(v, w.z, a2);
        a3 = fmaf(v, w.w, a3);
    }
    #pragma unroll
    for (int off = 16; off > 0; off >>= 1) {
        a0 += __shfl_xor_sync(0xffffffffu, a0, off);
        a1 += __shfl_xor_sync(0xffffffffu, a1, off);
        a2 += __shfl_xor_sync(0xffffffffu, a2, off);
        a3 += __shfl_xor_sync(0xffffffffu, a3, off);
    }
    __shared__ float sred[8][4];
    int lane = tid & 31, warp = tid >> 5;
    if (lane == 0) {
        sred[warp][0] = a0; sred[warp][1] = a1;
        sred[warp][2] = a2; sred[warp][3] = a3;
    }
    __syncthreads();
    if (tid == 0) {
        float l[4];
        #pragma unroll
        for (int c = 0; c < 4; c++) {
            float s = bfc[c];
            #pragma unroll
            for (int w = 0; w < 8; w++) s += sred[w][c];
            l[c] = s;
        }
        float m = fmaxf(fmaxf(l[0], l[1]), fmaxf(l[2], l[3]));
        float e0 = __expf(l[0] - m), e1 = __expf(l[1] - m);
        float e2 = __expf(l[2] - m), e3 = __expf(l[3] - m);
        float inv = 1.0f / (e0 + e1 + e2 + e3);
        out[g * 4 + 0] = e0 * inv;
        out[g * 4 + 1] = e1 * inv;
        out[g * 4 + 2] = e2 * inv;
        out[g * 4 + 3] = e3 * inv;
    }
}

// ---------------- launch ----------------
extern "C" void kernel_launch(void* const* d_in, const int* in_sizes, int n_in,
                              void* d_out, int out_size) {
    const float* x   = (const float*)d_in[0];
    const int*   ei  = (const int*)d_in[1];
    const float* ew  = (const float*)d_in[2];
    const float* W1  = (const float*)d_in[3];
    const float* b1  = (const float*)d_in[4];
    const float* W2  = (const float*)d_in[5];
    const float* b2  = (const float*)d_in[6];
    const float* Wfc = (const float*)d_in[7];
    const float* bfc = (const float*)d_in[8];
    float* out = (float*)d_out;

    __half* xh;  cudaGetSymbolAddress((void**)&xh, g_xh);
    float* aggx; cudaGetSymbolAddress((void**)&aggx, g_aggx);
    float* h1;   cudaGetSymbolAddress((void**)&h1, g_h1);
    __half* h2h; cudaGetSymbolAddress((void**)&h2h, g_h2h);
    float* h2;   cudaGetSymbolAddress((void**)&h2, g_h2);

    const int smem1 = (128 * 68 + 64 * 136) * 4;
    const int smem2 = (128 * 132 + 128 * 72) * 4;
    cudaFuncSetAttribute(gemm_tc<64, 128, true, false>,
                         cudaFuncAttributeMaxDynamicSharedMemorySize, smem1);
    cudaFuncSetAttribute(gemm_tc<128, 64, false, true>,
                         cudaFuncAttributeMaxDynamicSharedMemorySize, smem2);

    // CSR build (launch order puts k_scatter at index 5 for ncu -s 5 -c 1 visibility)
    k_init<<<NN / 256, 256>>>();                      // 0
    k_deg_hist<<<EE / 256, 256>>>(ei, ew);            // 1
    k_scan1<<<128, 256>>>();                          // 2
    k_scan2<<<1, 128>>>();                            // 3
    k_scan3_dis<<<NN / 256, 256>>>();                 // 4
    k_scatter<<<EE / 256, 256>>>(ei, ew);             // 5  <- profiled
    k_x2h<<<NN * 16 / 256, 256>>>(x);                 // 6

    // layer 1: aggregate x (fp16 gathers), then TC GEMM (64->128) + bias + relu
    k_agg_csr_h<<<NN / 8, 256>>>(xh, aggx);
    gemm_tc<64, 128, true, false><<<NN / 128, 256, smem1>>>(aggx, W1, b1, h1);

    // layer 2: TC GEMM (128->64) -> fp16, then aggregate; bias/relu deferred to FC
    gemm_tc<128, 64, false, true><<<NN / 128, 256, smem2>>>(h1, W2, nullptr, h2h);
    k_agg_csr_h<<<NN / 8, 256>>>(h2h, h2);

    // FC + softmax
    fc_softmax<<<1024, 256>>>(h2, Wfc, bfc, b2, out);
}

// round 14
// speedup vs baseline: 1.0862x; 1.0862x over previous
#include <cuda_runtime.h>
#include <cuda_bf16.h>
#include <cuda_fp16.h>
#include <cstdint>

#define NN 131072
#define EE 2097152

// ---------------- device scratch (static; no allocation allowed) ----------------
__device__ float2 g_dc[NN];            // (deg accumulator, count accumulator)
__device__ float  g_dis[NN];           // rsqrt(deg)
__device__ int    g_cnt[NN];           // int count
__device__ int    g_rowptr[NN];        // exclusive scan of counts
__device__ int    g_cur[NN];           // scatter cursor
__device__ int    g_blksum[128];
__device__ int2   g_csr[EE];           // (src, __float_as_int(norm)), grouped by dst
__device__ __half g_xh[NN * 64];       // fp16 copy of x (one 128B line per node)
__device__ float  g_aggx[NN * 64];     // A_norm @ x  (fp32 for GEMM)
__device__ __half g_h2h[NN * 64];      // relu(agg@W1+b1)@W2  (fp16 for agg2 gathers)
__device__ float  g_h2[NN * 64];       // A_norm @ h2t (fp32 for FC)

// ---------------- init (launched as two halves for profiler indexing) ----------------
__global__ void k_init(int base) {
    int i = base + blockIdx.x * blockDim.x + threadIdx.x;
    if (i < NN) g_dc[i] = make_float2(1.0f, 0.0f);   // self-loop weight = 1
}

// ---------------- degree + histogram: ONE vector reduction per edge ----------------
__global__ void k_deg_hist(const int* __restrict__ ei, const float* __restrict__ ew) {
    int e = blockIdx.x * blockDim.x + threadIdx.x;
    if (e < EE) {
        int d = ei[EE + e];
        float w = ew[e];
        asm volatile("red.global.add.v2.f32 [%0], {%1,%2};"
                     :: "l"(&g_dc[d]), "f"(w), "f"(1.0f) : "memory");
    }
}

// ---------------- x -> fp16 (coalesced convert; independent of everything) ----------
__global__ void k_x2h(const float* __restrict__ X) {
    int t = blockIdx.x * blockDim.x + threadIdx.x;   // NN*16 threads, float4 each
    if (t >= NN * 16) return;
    float4 v = ((const float4*)X)[t];
    __half2* O = (__half2*)g_xh;
    O[2 * t]     = __floats2half2_rn(v.x, v.y);
    O[2 * t + 1] = __floats2half2_rn(v.z, v.w);
}

// ---------------- scan stage 1: per-1024-chunk exclusive scan + block sums ----------
__global__ void k_scan1() {
    __shared__ int warp_s[8];
    int b = blockIdx.x, t = threadIdx.x;
    int base = b * 1024 + t * 4;
    const float4* D4 = (const float4*)g_dc;
    float4 f0 = D4[base / 2];
    float4 f1 = D4[base / 2 + 1];
    int c0 = (int)f0.y, c1 = (int)f0.w, c2 = (int)f1.y, c3 = (int)f1.w;
    int s0 = c0, s1 = s0 + c1, s2 = s1 + c2, s3 = s2 + c3;
    int tsum = s3;
    int lane = t & 31, warp = t >> 5;
    int v = tsum;
    #pragma unroll
    for (int off = 1; off < 32; off <<= 1) {
        int u = __shfl_up_sync(0xffffffffu, v, off);
        if (lane >= off) v += u;
    }
    if (lane == 31) warp_s[warp] = v;
    __syncthreads();
    if (t < 8) {
        int x = warp_s[t];
        #pragma unroll
        for (int off = 1; off < 8; off <<= 1) {
            int u = __shfl_up_sync(0xffu, x, off);
            if (t >= off) x += u;
        }
        warp_s[t] = x;
    }
    __syncthreads();
    int woff = (warp > 0) ? warp_s[warp - 1] : 0;
    int texcl = woff + v - tsum;
    g_rowptr[base + 0] = texcl;
    g_rowptr[base + 1] = texcl + s0;
    g_rowptr[base + 2] = texcl + s1;
    g_rowptr[base + 3] = texcl + s2;
    if (t == 255) g_blksum[b] = woff + v;
}

// ---------------- scan stage 2+3 fused: every block scans the 128 block sums ------
__global__ void k_scan23() {
    __shared__ int s_bs[128];
    __shared__ int s_w[4];
    int t = threadIdx.x;
    if (t < 128) {
        int v = g_blksum[t];
        int lane = t & 31, w = t >> 5;
        int p = v;
        #pragma unroll
        for (int off = 1; off < 32; off <<= 1) {
            int u = __shfl_up_sync(0xffffffffu, p, off);
            if (lane >= off) p += u;
        }
        if (lane == 31) s_w[w] = p;
        s_bs[t] = p - v;                 // within-warp exclusive
    }
    __syncthreads();
    if (t < 128) {
        int w = t >> 5;
        int woff = 0;
        for (int k = 0; k < w; k++) woff += s_w[k];
        s_bs[t] += woff;                 // global exclusive block offset
    }
    __syncthreads();
    int i = blockIdx.x * 256 + t;        // 512 blocks x 256 = NN
    int r = g_rowptr[i] + s_bs[i >> 10];
    g_rowptr[i] = r;
    g_cur[i] = r;
    float2 dc = g_dc[i];
    g_dis[i] = rsqrtf(dc.x);             // deg >= 1 (self-loop)
    g_cnt[i] = (int)dc.y;
}

// ---------------- scatter edges into CSR, norm computed inline ----------------
__global__ void k_scatter(const int* __restrict__ ei, const float* __restrict__ ew) {
    int e = blockIdx.x * blockDim.x + threadIdx.x;
    if (e >= EE) return;
    int s = ei[e], d = ei[EE + e];
    float nrm = g_dis[s] * ew[e] * g_dis[d];
    int pos = atomicAdd(&g_cur[d], 1);
    g_csr[pos] = make_int2(s, __float_as_int(nrm));
}

// ---------------- CSR gather aggregation (fp16 in, fp32 out): one warp/node --------
__global__ void k_agg_csr_h(const __half* __restrict__ Xh, float* __restrict__ Out) {
    int warp = threadIdx.x >> 5;
    int lane = threadIdx.x & 31;
    int node = blockIdx.x * 8 + warp;
    const __half2* X2 = (const __half2*)Xh;

    float sn = g_dis[node];
    sn = sn * sn;
    float2 xs = __half22float2(X2[node * 32 + lane]);
    float2 acc0 = make_float2(sn * xs.x, sn * xs.y);
    float2 acc1 = make_float2(0.f, 0.f);

    int beg = g_rowptr[node];
    int deg = g_cnt[node];

    for (int base = 0; base < deg; base += 32) {
        int n = min(32, deg - base);
        int2 entry = make_int2(0, 0);
        if (lane < n) entry = g_csr[beg + base + lane];   // coalesced
        int j = 0;
        #pragma unroll 2
        for (; j + 2 <= n; j += 2) {
            int s0 = __shfl_sync(0xffffffffu, entry.x, j);
            int b0 = __shfl_sync(0xffffffffu, entry.y, j);
            int s1 = __shfl_sync(0xffffffffu, entry.x, j + 1);
            int b1 = __shfl_sync(0xffffffffu, entry.y, j + 1);
            float2 v0 = __half22float2(X2[s0 * 32 + lane]);
            float2 v1 = __half22float2(X2[s1 * 32 + lane]);
            float n0 = __int_as_float(b0);
            float n1 = __int_as_float(b1);
            acc0.x = fmaf(n0, v0.x, acc0.x);
            acc0.y = fmaf(n0, v0.y, acc0.y);
            acc1.x = fmaf(n1, v1.x, acc1.x);
            acc1.y = fmaf(n1, v1.y, acc1.y);
        }
        if (j < n) {
            int s0 = __shfl_sync(0xffffffffu, entry.x, j);
            int b0 = __shfl_sync(0xffffffffu, entry.y, j);
            float2 v0 = __half22float2(X2[s0 * 32 + lane]);
            float n0 = __int_as_float(b0);
            acc0.x = fmaf(n0, v0.x, acc0.x);
            acc0.y = fmaf(n0, v0.y, acc0.y);
        }
    }
    acc0.x += acc1.x;
    acc0.y += acc1.y;
    ((float2*)Out)[node * 32 + lane] = acc0;
}

// ---------------- tf32 helpers ----------------
__device__ __forceinline__ unsigned int cvt_tf32(float f) {
    unsigned int o;
    asm("cvt.rna.tf32.f32 %0, %1;" : "=r"(o) : "f"(f));
    return o;
}

__device__ __forceinline__ void mma_tf32(float* c, unsigned int a0, unsigned int a1,
                                         unsigned int a2, unsigned int a3,
                                         unsigned int b0, unsigned int b1) {
    asm volatile("mma.sync.aligned.m16n8k8.row.col.f32.tf32.tf32.f32 "
                 "{%0,%1,%2,%3}, {%4,%5,%6,%7}, {%8,%9}, {%0,%1,%2,%3};"
                 : "+f"(c[0]), "+f"(c[1]), "+f"(c[2]), "+f"(c[3])
                 : "r"(a0), "r"(a1), "r"(a2), "r"(a3), "r"(b0), "r"(b1));
}

// ---------------- fused double GEMM: h2h = (relu(X@W1+b1)) @ W2, fp16 out ----------
// Block: 256 threads (8 warps), 128-row tile. Stage1: K=64,NC=128. Stage2: K=128,NC=64.
// smem (floats): sX[0,8704) sW1[8704,17408) sW2[17408,26624); sT1 aliases [0,16896).
__global__ void gemm12(const float* __restrict__ X, const float* __restrict__ W1,
                       const float* __restrict__ b1, const float* __restrict__ W2,
                       __half* __restrict__ Yh) {
    extern __shared__ float smem[];
    float* sX  = smem;            // 128 x 68
    float* sW1 = smem + 8704;     // 64 x 136
    float* sW2 = smem + 17408;    // 128 x 72
    float* sT1 = smem;            // 128 x 132 (aliases sX/sW1 after stage 1)

    int tid = threadIdx.x, lane = tid & 31, warp = tid >> 5;
    int row0 = blockIdx.x * 128;

    // stage loads
    #pragma unroll 4
    for (int idx = tid; idx < 128 * 16; idx += 256) {          // X tile 128x64
        int r = idx / 16, c4 = idx % 16;
        float4 v = ((const float4*)(X + (size_t)(row0 + r) * 64))[c4];
        *(float4*)&sX[r * 68 + c4 * 4] = v;
    }
    #pragma unroll 4
    for (int idx = tid; idx < 64 * 32; idx += 256) {           // W1 64x128
        int r = idx / 32, c4 = idx % 32;
        float4 v = ((const float4*)(W1 + r * 128))[c4];
        *(float4*)&sW1[r * 136 + c4 * 4] = v;
    }
    #pragma unroll 4
    for (int idx = tid; idx < 128 * 16; idx += 256) {          // W2 128x64
        int r = idx / 16, c4 = idx % 16;
        float4 v = ((const float4*)(W2 + r * 64))[c4];
        *(float4*)&sW2[r * 72 + c4 * 4] = v;
    }
    __syncthreads();

    int ar = warp * 16 + (lane >> 2);
    int ak = lane & 3;
    int bk = lane & 3;
    int bn = lane >> 2;

    // ---- stage 1: acc1[16][4] = X @ W1 ----
    float acc1[16][4];
    #pragma unroll
    for (int t = 0; t < 16; t++)
        #pragma unroll
        for (int i = 0; i < 4; i++) acc1[t][i] = 0.0f;

    #pragma unroll
    for (int ks = 0; ks < 8; ks++) {
        int k0 = ks * 8;
        unsigned int a0 = cvt_tf32(sX[ar * 68 + k0 + ak]);
        unsigned int a1 = cvt_tf32(sX[(ar + 8) * 68 + k0 + ak]);
        unsigned int a2 = cvt_tf32(sX[ar * 68 + k0 + ak + 4]);
        unsigned int a3 = cvt_tf32(sX[(ar + 8) * 68 + k0 + ak + 4]);
        #pragma unroll
        for (int t = 0; t < 16; t++) {
            unsigned int b0 = cvt_tf32(sW1[(k0 + bk) * 136 + t * 8 + bn]);
            unsigned int b1 = cvt_tf32(sW1[(k0 + bk + 4) * 136 + t * 8 + bn]);
            mma_tf32(acc1[t], a0, a1, a2, a3, b0, b1);
        }
    }
    __syncthreads();   // all reads of sX/sW1 done

    // ---- write T1 = relu(acc1 + b1) into sT1 ----
    #pragma unroll
    for (int t = 0; t < 16; t++) {
        int col = t * 8 + 2 * (lane & 3);
        float bb0 = b1[col], bb1 = b1[col + 1];
        sT1[ar * 132 + col]           = fmaxf(acc1[t][0] + bb0, 0.f);
        sT1[ar * 132 + col + 1]       = fmaxf(acc1[t][1] + bb1, 0.f);
        sT1[(ar + 8) * 132 + col]     = fmaxf(acc1[t][2] + bb0, 0.f);
        sT1[(ar + 8) * 132 + col + 1] = fmaxf(acc1[t][3] + bb1, 0.f);
    }
    __syncthreads();

    // ---- stage 2: acc2[8][4] = T1 @ W2 ----
    float acc2[8][4];
    #pragma unroll
    for (int t = 0; t < 8; t++)
        #pragma unroll
        for (int i = 0; i < 4; i++) acc2[t][i] = 0.0f;

    #pragma unroll
    for (int ks = 0; ks < 16; ks++) {
        int k0 = ks * 8;
        unsigned int a0 = cvt_tf32(sT1[ar * 132 + k0 + ak]);
        unsigned int a1 = cvt_tf32(sT1[(ar + 8) * 132 + k0 + ak]);
        unsigned int a2 = cvt_tf32(sT1[ar * 132 + k0 + ak + 4]);
        unsigned int a3 = cvt_tf32(sT1[(ar + 8) * 132 + k0 + ak + 4]);
        #pragma unroll
        for (int t = 0; t < 8; t++) {
            unsigned int b0 = cvt_tf32(sW2[(k0 + bk) * 72 + t * 8 + bn]);
            unsigned int b1 = cvt_tf32(sW2[(k0 + bk + 4) * 72 + t * 8 + bn]);
            mma_tf32(acc2[t], a0, a1, a2, a3, b0, b1);
        }
    }

    // ---- epilogue: fp16 out ----
    int orow = row0 + ar;
    __half2* Y2 = (__half2*)Yh;
    #pragma unroll
    for (int t = 0; t < 8; t++) {
        int col = t * 8 + 2 * (lane & 3);
        Y2[((size_t)orow * 64 + col) / 2]       = __floats2half2_rn(acc2[t][0], acc2[t][1]);
        Y2[((size_t)(orow + 8) * 64 + col) / 2] = __floats2half2_rn(acc2[t][2], acc2[t][3]);
    }
}

// ---------------- FC + softmax (fuses layer-2 bias + relu) ----------------
__global__ void fc_softmax(const float* __restrict__ H, const float* __restrict__ Wfc,
                           const float* __restrict__ bfc, const float* __restrict__ b2,
                           float* __restrict__ out) {
    int g = blockIdx.x;
    int tid = threadIdx.x;      // 256
    const float* hrow = H + g * 8192;

    float a0 = 0.f, a1 = 0.f, a2 = 0.f, a3 = 0.f;
    for (int j = tid; j < 8192; j += 256) {
        float v = hrow[j] + b2[j & 63];
        v = fmaxf(v, 0.f);
        float4 w = __ldg((const float4*)Wfc + j);
        a0 = fmaf(v, w.x, a0);
        a1 = fmaf(v, w.y, a1);
        a2 = fmaf(v, w.z, a2);
        a3 = fmaf(v, w.w, a3);
    }
    #pragma unroll
    for (int off = 16; off > 0; off >>= 1) {
        a0 += __shfl_xor_sync(0xffffffffu, a0, off);
        a1 += __shfl_xor_sync(0xffffffffu, a1, off);
        a2 += __shfl_xor_sync(0xffffffffu, a2, off);
        a3 += __shfl_xor_sync(0xffffffffu, a3, off);
    }
    __shared__ float sred[8][4];
    int lane = tid & 31, warp = tid >> 5;
    if (lane == 0) {
        sred[warp][0] = a0; sred[warp][1] = a1;
        sred[warp][2] = a2; sred[warp][3] = a3;
    }
    __syncthreads();
    if (tid == 0) {
        float l[4];
        #pragma unroll
        for (int c = 0; c < 4; c++) {
            float s = bfc[c];
            #pragma unroll
            for (int w = 0; w < 8; w++) s += sred[w][c];
            l[c] = s;
        }
        float m = fmaxf(fmaxf(l[0], l[1]), fmaxf(l[2], l[3]));
        float e0 = __expf(l[0] - m), e1 = __expf(l[1] - m);
        float e2 = __expf(l[2] - m), e3 = __expf(l[3] - m);
        float inv = 1.0f / (e0 + e1 + e2 + e3);
        out[g * 4 + 0] = e0 * inv;
        out[g * 4 + 1] = e1 * inv;
        out[g * 4 + 2] = e2 * inv;
        out[g * 4 + 3] = e3 * inv;
    }
}

// ---------------- launch ----------------
extern "C" void kernel_launch(void* const* d_in, const int* in_sizes, int n_in,
                              void* d_out, int out_size) {
    const float* x   = (const float*)d_in[0];
    const int*   ei  = (const int*)d_in[1];
    const float* ew  = (const float*)d_in[2];
    const float* W1  = (const float*)d_in[3];
    const float* b1  = (const float*)d_in[4];
    const float* W2  = (const float*)d_in[5];
    const float* b2  = (const float*)d_in[6];
    const float* Wfc = (const float*)d_in[7];
    const float* bfc = (const float*)d_in[8];
    float* out = (float*)d_out;

    __half* xh;  cudaGetSymbolAddress((void**)&xh, g_xh);
    float* aggx; cudaGetSymbolAddress((void**)&aggx, g_aggx);
    __half* h2h; cudaGetSymbolAddress((void**)&h2h, g_h2h);
    float* h2;   cudaGetSymbolAddress((void**)&h2, g_h2);

    const int smem12 = 26624 * 4;   // 104 KB
    cudaFuncSetAttribute(gemm12, cudaFuncAttributeMaxDynamicSharedMemorySize, smem12);

    // CSR build; launch index 3 == k_deg_hist so ncu finally profiles a heavy kernel
    k_x2h<<<NN * 16 / 256, 256>>>(x);              // 0 (independent)
    k_init<<<NN / 512, 256>>>(0);                  // 1 (first half)
    k_init<<<NN / 512, 256>>>(NN / 2);             // 2 (second half)
    k_deg_hist<<<EE / 256, 256>>>(ei, ew);         // 3  <- profiled
    k_scan1<<<128, 256>>>();                       // 4
    k_scan23<<<NN / 256, 256>>>();                 // 5
    k_scatter<<<EE / 256, 256>>>(ei, ew);          // 6

    // layer 1 aggregate (fp16 gathers) -> fused double GEMM -> fp16 h2
    k_agg_csr_h<<<NN / 8, 256>>>(xh, aggx);
    gemm12<<<NN / 128, 256, smem12>>>(aggx, W1, b1, W2, h2h);

    // layer 2 aggregate, then FC + softmax
    k_agg_csr_h<<<NN / 8, 256>>>(h2h, h2);
    fc_softmax<<<1024, 256>>>(h2, Wfc, bfc, b2, out);
}

// round 15
// speedup vs baseline: 1.1768x; 1.0834x over previous
#include <cuda_runtime.h>
#include <cuda_bf16.h>
#include <cuda_fp16.h>
#include <cstdint>

#define NN 131072
#define EE 2097152

// ---------------- device scratch (static; no allocation allowed) ----------------
__device__ float2 g_dc[NN];            // (deg accumulator, count accumulator)
__device__ float  g_dis[NN];           // rsqrt(deg)
__device__ int    g_cnt[NN];           // int count
__device__ int    g_rowptr[NN];        // exclusive scan of counts
__device__ int    g_cur[NN];           // scatter cursor
__device__ int    g_blksum[128];
__device__ int2   g_csr[EE];           // (src, __float_as_int(dis[s]*w)), grouped by dst
__device__ __half g_aggh[NN * 64];     // A_norm @ x        (fp16)
__device__ __half g_h2h[NN * 64];      // relu(agg@W1+b1)@W2 (fp16)
__device__ __half g_h3h[NN * 64];      // A_norm @ h2t       (fp16, for FC)

// ---------------- init ----------------
__global__ void k_init() {
    int i = blockIdx.x * blockDim.x + threadIdx.x;
    if (i < NN) g_dc[i] = make_float2(1.0f, 0.0f);   // self-loop weight = 1
}

// ---------------- degree + histogram: ONE vector reduction per edge ----------------
__global__ void k_deg_hist(const int* __restrict__ ei, const float* __restrict__ ew) {
    int e = blockIdx.x * blockDim.x + threadIdx.x;
    if (e < EE) {
        int d = ei[EE + e];
        float w = ew[e];
        asm volatile("red.global.add.v2.f32 [%0], {%1,%2};"
                     :: "l"(&g_dc[d]), "f"(w), "f"(1.0f) : "memory");
    }
}

// ---------------- scan stage 1 ----------------
__global__ void k_scan1() {
    __shared__ int warp_s[8];
    int b = blockIdx.x, t = threadIdx.x;
    int base = b * 1024 + t * 4;
    const float4* D4 = (const float4*)g_dc;
    float4 f0 = D4[base / 2];
    float4 f1 = D4[base / 2 + 1];
    int c0 = (int)f0.y, c1 = (int)f0.w, c2 = (int)f1.y, c3 = (int)f1.w;
    int s0 = c0, s1 = s0 + c1, s2 = s1 + c2, s3 = s2 + c3;
    int tsum = s3;
    int lane = t & 31, warp = t >> 5;
    int v = tsum;
    #pragma unroll
    for (int off = 1; off < 32; off <<= 1) {
        int u = __shfl_up_sync(0xffffffffu, v, off);
        if (lane >= off) v += u;
    }
    if (lane == 31) warp_s[warp] = v;
    __syncthreads();
    if (t < 8) {
        int x = warp_s[t];
        #pragma unroll
        for (int off = 1; off < 8; off <<= 1) {
            int u = __shfl_up_sync(0xffu, x, off);
            if (t >= off) x += u;
        }
        warp_s[t] = x;
    }
    __syncthreads();
    int woff = (warp > 0) ? warp_s[warp - 1] : 0;
    int texcl = woff + v - tsum;
    g_rowptr[base + 0] = texcl;
    g_rowptr[base + 1] = texcl + s0;
    g_rowptr[base + 2] = texcl + s1;
    g_rowptr[base + 3] = texcl + s2;
    if (t == 255) g_blksum[b] = woff + v;
}

// ---------------- scan stage 2+3 fused ----------------
__global__ void k_scan23() {
    __shared__ int s_bs[128];
    __shared__ int s_w[4];
    int t = threadIdx.x;
    if (t < 128) {
        int v = g_blksum[t];
        int lane = t & 31, w = t >> 5;
        int p = v;
        #pragma unroll
        for (int off = 1; off < 32; off <<= 1) {
            int u = __shfl_up_sync(0xffffffffu, p, off);
            if (lane >= off) p += u;
        }
        if (lane == 31) s_w[w] = p;
        s_bs[t] = p - v;
    }
    __syncthreads();
    if (t < 128) {
        int w = t >> 5;
        int woff = 0;
        for (int k = 0; k < w; k++) woff += s_w[k];
        s_bs[t] += woff;
    }
    __syncthreads();
    int i = blockIdx.x * 256 + t;
    int r = g_rowptr[i] + s_bs[i >> 10];
    g_rowptr[i] = r;
    g_cur[i] = r;
    float2 dc = g_dc[i];
    g_dis[i] = rsqrtf(dc.x);
    g_cnt[i] = (int)dc.y;
}

// ---------------- scatter: payload = dis[s]*w (dis[d] factored into agg) ------------
__global__ void k_scatter(const int* __restrict__ ei, const float* __restrict__ ew) {
    int e = blockIdx.x * blockDim.x + threadIdx.x;
    if (e >= EE) return;
    int s = ei[e], d = ei[EE + e];
    float p = g_dis[s] * ew[e];
    int pos = atomicAdd(&g_cur[d], 1);
    g_csr[pos] = make_int2(s, __float_as_int(p));
}

// ---------------- CSR gather aggregation: one warp/node, fp16 out ----------------
// out[d] = dis[d] * ( dis[d]*x[d] + sum_e p_e * x[src_e] )
template<bool IN_HALF>
__global__ void k_agg(const void* __restrict__ Xv, __half* __restrict__ Out) {
    int warp = threadIdx.x >> 5;
    int lane = threadIdx.x & 31;
    int node = blockIdx.x * 8 + warp;

    auto ldrow = [&](int row) -> float2 {
        if (IN_HALF) return __half22float2(((const __half2*)Xv)[row * 32 + lane]);
        else         return ((const float2*)Xv)[row * 32 + lane];
    };

    float dn = g_dis[node];
    float2 xs = ldrow(node);
    float2 acc0 = make_float2(dn * xs.x, dn * xs.y);
    float2 acc1 = make_float2(0.f, 0.f);

    int beg = g_rowptr[node];
    int deg = g_cnt[node];

    for (int base = 0; base < deg; base += 32) {
        int n = min(32, deg - base);
        int2 entry = make_int2(0, 0);
        if (lane < n) entry = g_csr[beg + base + lane];   // coalesced
        int j = 0;
        #pragma unroll 2
        for (; j + 2 <= n; j += 2) {
            int s0 = __shfl_sync(0xffffffffu, entry.x, j);
            int b0 = __shfl_sync(0xffffffffu, entry.y, j);
            int s1 = __shfl_sync(0xffffffffu, entry.x, j + 1);
            int b1 = __shfl_sync(0xffffffffu, entry.y, j + 1);
            float2 v0 = ldrow(s0);
            float2 v1 = ldrow(s1);
            float n0 = __int_as_float(b0);
            float n1 = __int_as_float(b1);
            acc0.x = fmaf(n0, v0.x, acc0.x);
            acc0.y = fmaf(n0, v0.y, acc0.y);
            acc1.x = fmaf(n1, v1.x, acc1.x);
            acc1.y = fmaf(n1, v1.y, acc1.y);
        }
        if (j < n) {
            int s0 = __shfl_sync(0xffffffffu, entry.x, j);
            int b0 = __shfl_sync(0xffffffffu, entry.y, j);
            float2 v0 = ldrow(s0);
            float n0 = __int_as_float(b0);
            acc0.x = fmaf(n0, v0.x, acc0.x);
            acc0.y = fmaf(n0, v0.y, acc0.y);
        }
    }
    float ox = dn * (acc0.x + acc1.x);
    float oy = dn * (acc0.y + acc1.y);
    ((__half2*)Out)[node * 32 + lane] = __floats2half2_rn(ox, oy);
}

// ---------------- tf32 helpers ----------------
__device__ __forceinline__ unsigned int cvt_tf32(float f) {
    unsigned int o;
    asm("cvt.rna.tf32.f32 %0, %1;" : "=r"(o) : "f"(f));
    return o;
}

__device__ __forceinline__ void mma_tf32(float* c, unsigned int a0, unsigned int a1,
                                         unsigned int a2, unsigned int a3,
                                         unsigned int b0, unsigned int b1) {
    asm volatile("mma.sync.aligned.m16n8k8.row.col.f32.tf32.tf32.f32 "
                 "{%0,%1,%2,%3}, {%4,%5,%6,%7}, {%8,%9}, {%0,%1,%2,%3};"
                 : "+f"(c[0]), "+f"(c[1]), "+f"(c[2]), "+f"(c[3])
                 : "r"(a0), "r"(a1), "r"(a2), "r"(a3), "r"(b0), "r"(b1));
}

// ---------------- fused double GEMM: h2h = (relu(X@W1+b1)) @ W2, fp16 in/out --------
__global__ void gemm12(const __half* __restrict__ X, const float* __restrict__ W1,
                       const float* __restrict__ b1, const float* __restrict__ W2,
                       __half* __restrict__ Yh) {
    extern __shared__ float smem[];
    float* sX  = smem;            // 128 x 68
    float* sW1 = smem + 8704;     // 64 x 136
    float* sW2 = smem + 17408;    // 128 x 72
    float* sT1 = smem;            // 128 x 132 (aliases sX/sW1 after stage 1)

    int tid = threadIdx.x, lane = tid & 31, warp = tid >> 5;
    int row0 = blockIdx.x * 128;

    // stage X tile (128x64 fp16 -> fp32 smem)
    const uint2* Xu = (const uint2*)X;             // 4 halves per uint2, 16 per row
    #pragma unroll 4
    for (int idx = tid; idx < 128 * 16; idx += 256) {
        int r = idx >> 4, c = idx & 15;
        uint2 u = Xu[(size_t)(row0 + r) * 16 + c];
        float2 f0 = __half22float2(*(__half2*)&u.x);
        float2 f1 = __half22float2(*(__half2*)&u.y);
        float* dst = &sX[r * 68 + c * 4];
        dst[0] = f0.x; dst[1] = f0.y; dst[2] = f1.x; dst[3] = f1.y;
    }
    #pragma unroll 4
    for (int idx = tid; idx < 64 * 32; idx += 256) {           // W1 64x128
        int r = idx / 32, c4 = idx % 32;
        float4 v = ((const float4*)(W1 + r * 128))[c4];
        *(float4*)&sW1[r * 136 + c4 * 4] = v;
    }
    #pragma unroll 4
    for (int idx = tid; idx < 128 * 16; idx += 256) {          // W2 128x64
        int r = idx / 16, c4 = idx % 16;
        float4 v = ((const float4*)(W2 + r * 64))[c4];
        *(float4*)&sW2[r * 72 + c4 * 4] = v;
    }
    __syncthreads();

    int ar = warp * 16 + (lane >> 2);
    int ak = lane & 3;
    int bk = lane & 3;
    int bn = lane >> 2;

    // ---- stage 1: acc1 = X @ W1 ----
    float acc1[16][4];
    #pragma unroll
    for (int t = 0; t < 16; t++)
        #pragma unroll
        for (int i = 0; i < 4; i++) acc1[t][i] = 0.0f;

    #pragma unroll
    for (int ks = 0; ks < 8; ks++) {
        int k0 = ks * 8;
        unsigned int a0 = cvt_tf32(sX[ar * 68 + k0 + ak]);
        unsigned int a1 = cvt_tf32(sX[(ar + 8) * 68 + k0 + ak]);
        unsigned int a2 = cvt_tf32(sX[ar * 68 + k0 + ak + 4]);
        unsigned int a3 = cvt_tf32(sX[(ar + 8) * 68 + k0 + ak + 4]);
        #pragma unroll
        for (int t = 0; t < 16; t++) {
            unsigned int b0 = cvt_tf32(sW1[(k0 + bk) * 136 + t * 8 + bn]);
            unsigned int b1 = cvt_tf32(sW1[(k0 + bk + 4) * 136 + t * 8 + bn]);
            mma_tf32(acc1[t], a0, a1, a2, a3, b0, b1);
        }
    }
    __syncthreads();

    // ---- T1 = relu(acc1 + b1) -> sT1 ----
    #pragma unroll
    for (int t = 0; t < 16; t++) {
        int col = t * 8 + 2 * (lane & 3);
        float bb0 = b1[col], bb1 = b1[col + 1];
        sT1[ar * 132 + col]           = fmaxf(acc1[t][0] + bb0, 0.f);
        sT1[ar * 132 + col + 1]       = fmaxf(acc1[t][1] + bb1, 0.f);
        sT1[(ar + 8) * 132 + col]     = fmaxf(acc1[t][2] + bb0, 0.f);
        sT1[(ar + 8) * 132 + col + 1] = fmaxf(acc1[t][3] + bb1, 0.f);
    }
    __syncthreads();

    // ---- stage 2: acc2 = T1 @ W2 ----
    float acc2[8][4];
    #pragma unroll
    for (int t = 0; t < 8; t++)
        #pragma unroll
        for (int i = 0; i < 4; i++) acc2[t][i] = 0.0f;

    #pragma unroll
    for (int ks = 0; ks < 16; ks++) {
        int k0 = ks * 8;
        unsigned int a0 = cvt_tf32(sT1[ar * 132 + k0 + ak]);
        unsigned int a1 = cvt_tf32(sT1[(ar + 8) * 132 + k0 + ak]);
        unsigned int a2 = cvt_tf32(sT1[ar * 132 + k0 + ak + 4]);
        unsigned int a3 = cvt_tf32(sT1[(ar + 8) * 132 + k0 + ak + 4]);
        #pragma unroll
        for (int t = 0; t < 8; t++) {
            unsigned int b0 = cvt_tf32(sW2[(k0 + bk) * 72 + t * 8 + bn]);
            unsigned int b1 = cvt_tf32(sW2[(k0 + bk + 4) * 72 + t * 8 + bn]);
            mma_tf32(acc2[t], a0, a1, a2, a3, b0, b1);
        }
    }

    // ---- epilogue: fp16 out ----
    int orow = row0 + ar;
    __half2* Y2 = (__half2*)Yh;
    #pragma unroll
    for (int t = 0; t < 8; t++) {
        int col = t * 8 + 2 * (lane & 3);
        Y2[((size_t)orow * 64 + col) / 2]       = __floats2half2_rn(acc2[t][0], acc2[t][1]);
        Y2[((size_t)(orow + 8) * 64 + col) / 2] = __floats2half2_rn(acc2[t][2], acc2[t][3]);
    }
}

// ---------------- FC + softmax, 8 graphs per block (Wfc register reuse) -------------
__global__ void fc_softmax8(const __half* __restrict__ H, const float* __restrict__ Wfc,
                            const float* __restrict__ bfc, const float* __restrict__ b2,
                            float* __restrict__ out) {
    int g0 = blockIdx.x * 8;                  // 128 blocks
    int tid = threadIdx.x;                    // 256
    int lane = tid & 31, warp = tid >> 5;

    __shared__ float s_b2[64];
    if (tid < 64) s_b2[tid] = b2[tid];
    __syncthreads();

    float acc[8][4];
    #pragma unroll
    for (int gi = 0; gi < 8; gi++)
        #pragma unroll
        for (int c = 0; c < 4; c++) acc[gi][c] = 0.0f;

    #pragma unroll 2
    for (int k = 0; k < 8; k++) {
        int j = (k * 256 + tid) * 4;          // element 0..8191, step 4
        float4 w0 = __ldg((const float4*)Wfc + j);
        float4 w1 = __ldg((const float4*)Wfc + j + 1);
        float4 w2 = __ldg((const float4*)Wfc + j + 2);
        float4 w3 = __ldg((const float4*)Wfc + j + 3);
        int jb = j & 63;
        float bb0 = s_b2[jb], bb1 = s_b2[jb + 1], bb2 = s_b2[jb + 2], bb3 = s_b2[jb + 3];
        #pragma unroll
        for (int gi = 0; gi < 8; gi++) {
            const __half2* hp = (const __half2*)(H + (size_t)(g0 + gi) * 8192 + j);
            float2 h0 = __half22float2(hp[0]);
            float2 h1 = __half22float2(hp[1]);
            float v0 = fmaxf(h0.x + bb0, 0.f);
            float v1 = fmaxf(h0.y + bb1, 0.f);
            float v2 = fmaxf(h1.x + bb2, 0.f);
            float v3 = fmaxf(h1.y + bb3, 0.f);
            acc[gi][0] = fmaf(v0, w0.x, fmaf(v1, w1.x, fmaf(v2, w2.x, fmaf(v3, w3.x, acc[gi][0]))));
            acc[gi][1] = fmaf(v0, w0.y, fmaf(v1, w1.y, fmaf(v2, w2.y, fmaf(v3, w3.y, acc[gi][1]))));
            acc[gi][2] = fmaf(v0, w0.z, fmaf(v1, w1.z, fmaf(v2, w2.z, fmaf(v3, w3.z, acc[gi][2]))));
            acc[gi][3] = fmaf(v0, w0.w, fmaf(v1, w1.w, fmaf(v2, w2.w, fmaf(v3, w3.w, acc[gi][3]))));
        }
    }

    __shared__ float sred[8][8][4];           // warp, graph, class
    #pragma unroll
    for (int gi = 0; gi < 8; gi++) {
        float a0 = acc[gi][0], a1 = acc[gi][1], a2 = acc[gi][2], a3 = acc[gi][3];
        #pragma unroll
        for (int off = 16; off > 0; off >>= 1) {
            a0 += __shfl_xor_sync(0xffffffffu, a0, off);
            a1 += __shfl_xor_sync(0xffffffffu, a1, off);
            a2 += __shfl_xor_sync(0xffffffffu, a2, off);
            a3 += __shfl_xor_sync(0xffffffffu, a3, off);
        }
        if (lane == 0) {
            sred[warp][gi][0] = a0; sred[warp][gi][1] = a1;
            sred[warp][gi][2] = a2; sred[warp][gi][3] = a3;
        }
    }
    __syncthreads();
    if (tid < 8) {
        float l[4];
        #pragma unroll
        for (int c = 0; c < 4; c++) {
            float s = bfc[c];
            #pragma unroll
            for (int w = 0; w < 8; w++) s += sred[w][tid][c];
            l[c] = s;
        }
        float m = fmaxf(fmaxf(l[0], l[1]), fmaxf(l[2], l[3]));
        float e0 = __expf(l[0] - m), e1 = __expf(l[1] - m);
        float e2 = __expf(l[2] - m), e3 = __expf(l[3] - m);
        float inv = 1.0f / (e0 + e1 + e2 + e3);
        float* o = out + (size_t)(g0 + tid) * 4;
        o[0] = e0 * inv; o[1] = e1 * inv; o[2] = e2 * inv; o[3] = e3 * inv;
    }
}

// ---------------- launch ----------------
extern "C" void kernel_launch(void* const* d_in, const int* in_sizes, int n_in,
                              void* d_out, int out_size) {
    const float* x   = (const float*)d_in[0];
    const int*   ei  = (const int*)d_in[1];
    const float* ew  = (const float*)d_in[2];
    const float* W1  = (const float*)d_in[3];
    const float* b1  = (const float*)d_in[4];
    const float* W2  = (const float*)d_in[5];
    const float* b2  = (const float*)d_in[6];
    const float* Wfc = (const float*)d_in[7];
    const float* bfc = (const float*)d_in[8];
    float* out = (float*)d_out;

    __half* aggh; cudaGetSymbolAddress((void**)&aggh, g_aggh);
    __half* h2h;  cudaGetSymbolAddress((void**)&h2h, g_h2h);
    __half* h3h;  cudaGetSymbolAddress((void**)&h3h, g_h3h);

    const int smem12 = 26624 * 4;   // 104 KB
    cudaFuncSetAttribute(gemm12, cudaFuncAttributeMaxDynamicSharedMemorySize, smem12);

    // CSR build
    k_init<<<NN / 256, 256>>>();                   // 0
    k_deg_hist<<<EE / 256, 256>>>(ei, ew);         // 1
    k_scan1<<<128, 256>>>();                       // 2
    k_scan23<<<NN / 256, 256>>>();                 // 3
    k_scatter<<<EE / 256, 256>>>(ei, ew);          // 4

    // layer 1 aggregate (fp32 gathers from x, fp16 out) -> fused double GEMM (fp16 out)
    k_agg<false><<<NN / 8, 256>>>(x, aggh);        // 5
    gemm12<<<NN / 128, 256, smem12>>>(aggh, W1, b1, W2, h2h);   // 6

    // layer 2 aggregate (fp16 in/out), then batched FC + softmax
    k_agg<true><<<NN / 8, 256>>>(h2h, h3h);        // 7
    fc_softmax8<<<128, 256>>>(h3h, Wfc, bfc, b2, out);          // 8
}